// round 1
// baseline (speedup 1.0000x reference)
#include <cuda_runtime.h>
#include <cstdint>

// ROI adaptive average pooling, direct summation.
// x:    [B=8, C=64, H=256, W=256] fp32
// rois: [B=8, S=128, 5] int32  (idx, x1, y1, x2, y2) -- idx field ignored (ref vmaps over b)
// out:  [B, S*C, 7, 7] fp32 ; bin (oy,ox) of roi crop uses torch adaptive-pool bounds:
//   sy = y1 + floor(oy*h/7), ey = y1 + ceil((oy+1)*h/7)   (h = y2-y1), same for x.

namespace {
constexpr int B = 8;
constexpr int C = 64;
constexpr int H = 256;
constexpr int W = 256;
constexpr int S = 128;
constexpr int OH = 7;
constexpr int OW = 7;
constexpr int TOTAL = B * S * C * OH * OW;  // 3,211,264
}

__global__ void __launch_bounds__(256) roi_adaptive_pool_kernel(
    const float* __restrict__ x,
    const int* __restrict__ rois,
    float* __restrict__ out)
{
    int idx = blockIdx.x * blockDim.x + threadIdx.x;
    if (idx >= TOTAL) return;

    // idx = (((b*S + s)*C + c)*OH + oy)*OW + ox  -- matches output layout [B, S*C, 7, 7]
    int ox = idx % OW;
    int t  = idx / OW;
    int oy = t % OH;  t /= OH;
    int c  = t % C;   t /= C;
    int s  = t % S;
    int b  = t / S;

    const int* r = rois + (b * S + s) * 5;
    int x1 = r[1];
    int y1 = r[2];
    int x2 = r[3];
    int y2 = r[4];
    int h = y2 - y1;
    int w = x2 - x1;

    // torch adaptive bin boundaries (integer floor / ceil)
    int sy = y1 + (oy * h) / OH;
    int ey = y1 + ((oy + 1) * h + (OH - 1)) / OH;
    int sx = x1 + (ox * w) / OW;
    int ex = x1 + ((ox + 1) * w + (OW - 1)) / OW;

    const float* base = x + (size_t)(b * C + c) * (H * W);

    float acc = 0.0f;
    for (int y = sy; y < ey; ++y) {
        const float* row = base + y * W;
        #pragma unroll 4
        for (int xx = sx; xx < ex; ++xx) {
            acc += __ldg(row + xx);
        }
    }

    float area = (float)((ey - sy) * (ex - sx));
    out[idx] = acc / area;
}

extern "C" void kernel_launch(void* const* d_in, const int* in_sizes, int n_in,
                              void* d_out, int out_size)
{
    const float* x    = (const float*)d_in[0];
    const int*   rois = (const int*)d_in[1];
    float*       out  = (float*)d_out;

    int threads = 256;
    int blocks = (TOTAL + threads - 1) / threads;  // 12544
    roi_adaptive_pool_kernel<<<blocks, threads>>>(x, rois, out);
}